// round 14
// baseline (speedup 1.0000x reference)
#include <cuda_runtime.h>
#include <cuda_bf16.h>
#include <cstdint>

// ---------------- problem constants ----------------
#define BATCH 2
#define CCH   256
#define HH    192
#define WW    192
#define HW    (HH * WW)            // 36864
#define NTOT  (BATCH * HW)         // 73728
#define WP    (WW + 4)             // 196
#define HP    (HH + 4)             // 196

// GEMM chunk geometry: CTA 128(co) x 192(pix, full row), BK=32
#define NC1 40                     // K=1280
#define NC2 48                     // K=1536
#define CHUNK_A 4096               // floats per A chunk (32k x 128m), fragment-packed

// ---------------- device scratch ----------------
__device__ float g_xP  [BATCH * CCH * HH * WP + 64]; // NCHW w-padded(+2) tf32 (+slack)
__device__ float g_xC  [BATCH * CCH * HH * WW];      // NCHW plain tf32 (1x1 path)
__device__ float g_tmpP[BATCH * CCH * HP * WW];      // NCHW h-padded(+2) tf32
__device__ float g_feat[BATCH * HH * WW * CCH];      // NHWC fp32
__device__ float g_w15P[2 * NC1 * CHUNK_A];          // fragment-packed w15 (kw-major K)
__device__ float g_w51P[2 * NC2 * CHUNK_A];          // fragment-packed w51 (kh-major) + w11 tail

// ---------------- helpers ----------------
__device__ __forceinline__ float tf32r(float x) {
    uint32_t y;
    asm("cvt.rna.tf32.f32 %0, %1;" : "=r"(y) : "f"(x));
    return __uint_as_float(y);
}
__device__ __forceinline__ uint32_t smem_u32(const void* p) {
    uint32_t a;
    asm("{ .reg .u64 t; cvta.to.shared.u64 t, %1; cvt.u32.u64 %0, t; }" : "=r"(a) : "l"(p));
    return a;
}
#define CP_ASYNC16(dst, src) \
    asm volatile("cp.async.ca.shared.global [%0], [%1], 16;" :: "r"(dst), "l"(src))
#define CP_COMMIT()  asm volatile("cp.async.commit_group;")
#define CP_WAIT_1()  asm volatile("cp.async.wait_group 1;")
#define CP_WAIT_0()  asm volatile("cp.async.wait_group 0;")

__device__ __forceinline__ void mma_tf32(float* d, const uint32_t* a, const uint32_t* b) {
    asm volatile(
        "mma.sync.aligned.m16n8k8.row.col.f32.tf32.tf32.f32 "
        "{%0,%1,%2,%3}, {%4,%5,%6,%7}, {%8,%9}, {%0,%1,%2,%3};"
        : "+f"(d[0]), "+f"(d[1]), "+f"(d[2]), "+f"(d[3])
        : "r"(a[0]), "r"(a[1]), "r"(a[2]), "r"(a[3]), "r"(b[0]), "r"(b[1]));
}

// ---------------- prep kernels ----------------
__global__ __launch_bounds__(256) void pad_x_kernel(const float* __restrict__ x) {
    const int rows = BATCH * CCH * HH;
    const int wp = threadIdx.x;
    for (int row = blockIdx.x; row < rows; row += gridDim.x) {
        if (wp < WP) {
            float v = 0.f;
            if (wp >= 2 && wp < WW + 2)
                v = tf32r(x[(size_t)row * WW + (wp - 2)]);
            g_xP[(size_t)row * WP + wp] = v;
        }
    }
}

__global__ __launch_bounds__(256) void xc_kernel(const float* __restrict__ x) {
    const int N4 = BATCH * CCH * HW / 4;
    for (int id = blockIdx.x * blockDim.x + threadIdx.x; id < N4;
         id += gridDim.x * blockDim.x) {
        float4 v = reinterpret_cast<const float4*>(x)[id];
        v.x = tf32r(v.x); v.y = tf32r(v.y); v.z = tf32r(v.z); v.w = tf32r(v.w);
        reinterpret_cast<float4*>(g_xC)[id] = v;
    }
}

__global__ void zero_tmp_kernel() {
    const int N = BATCH * CCH * 4 * WW;
    for (int id = blockIdx.x * blockDim.x + threadIdx.x; id < N;
         id += gridDim.x * blockDim.x) {
        int w = id % WW, t = id / WW;
        int hs = t % 4,  bc = t / 4;
        int hpos = (hs < 2) ? hs : (hs + HH);
        g_tmpP[((size_t)bc * HP + hpos) * WW + w] = 0.f;
    }
}

// fragment-pack weights, K shift-major (gk = kshift*256 + ci), BK=32 chunks
__global__ void wpack_kernel(const float* __restrict__ w15,
                             const float* __restrict__ w51,
                             const float* __restrict__ w11) {
    const int N2 = 2 * NC2 * CHUNK_A;
    for (int id = blockIdx.x * blockDim.x + threadIdx.x; id < N2;
         id += gridDim.x * blockDim.x) {
        int reg  = id & 3;
        int lane = (id >> 2) & 31;
        int mi   = (id >> 7) & 3;
        int wm   = (id >> 9) & 1;
        int k8b  = (id >> 10) & 3;
        int rest = id >> 12;              // cb*NC2 + c
        int m_local = wm * 64 + mi * 16 + (lane >> 2) + ((reg & 1) << 3);
        int k_local = k8b * 8 + (lane & 3) + ((reg >> 1) << 2);
        int c  = rest % NC2;
        int cb = rest / NC2;
        int co = cb * 128 + m_local;
        int gk = c * 32 + k_local;
        float v;
        if (gk < 1280) {
            int kh = gk >> 8, ci = gk & 255;
            v = tf32r(w51[(co * CCH + ci) * 5 + kh]);
        } else {
            v = tf32r(w11[co * CCH + (gk - 1280)]);
        }
        g_w51P[id] = v;
    }
    const int N1 = 2 * NC1 * CHUNK_A;
    for (int id = blockIdx.x * blockDim.x + threadIdx.x; id < N1;
         id += gridDim.x * blockDim.x) {
        int reg  = id & 3;
        int lane = (id >> 2) & 31;
        int mi   = (id >> 7) & 3;
        int wm   = (id >> 9) & 1;
        int k8b  = (id >> 10) & 3;
        int rest = id >> 12;
        int c  = rest % NC1;
        int cb = rest / NC1;
        int m_local = wm * 64 + mi * 16 + (lane >> 2) + ((reg & 1) << 3);
        int k_local = k8b * 8 + (lane & 3) + ((reg >> 1) << 2);
        int co = cb * 128 + m_local;
        int gk = c * 32 + k_local;
        int kw = gk >> 8, ci = gk & 255;
        g_w15P[id] = tf32r(w15[(co * CCH + ci) * 5 + kw]);
    }
}

// ---------------- tf32 mma.sync GEMM ----------------
// stage: A packed 16384B + B row-major 32 x 200 floats (25600B); 3 stages
#define A_BYTES 16384
#define BSTRIDE 200                 // 200 % 32 == 8 -> conflict-free B reads
#define B_BYTES (32 * BSTRIDE * 4)  // 25600
#define STAGE_BYTES (A_BYTES + B_BYTES)   // 41984
#define NSTG 3
#define SMEM_DYN (NSTG * STAGE_BYTES)     // 125952

__global__ __launch_bounds__(256) void gemm_mma(
    int mode,
    const float* __restrict__ bias1,
    const float* __restrict__ bias2)
{
    extern __shared__ __align__(16) char smem[];
    const uint32_t sbase = smem_u32(smem);

    const int tid  = threadIdx.x;
    const int lane = tid & 31;
    const int warp = tid >> 5;
    const int wm = warp >> 2;          // 0..1
    const int wn = warp & 3;           // 0..3
    const int m0 = wm * 64;
    const int n0 = wn * 48;
    const int g  = lane >> 2;          // 0..7
    const int tq = lane & 3;           // 0..3

    const int p0 = blockIdx.x * 192;   // full row
    const int b  = p0 / HW;
    const int h  = (p0 % HW) / WW;
    const int cb = blockIdx.y;
    const int co0 = cb * 128;

    const int NC = (mode == 1) ? NC1 : NC2;
    const float* __restrict__ wsrc =
        (mode == 1) ? (g_w15P + (size_t)cb * NC1 * CHUNK_A)
                    : (g_w51P + (size_t)cb * NC2 * CHUNK_A);

    float acc[4][6][4];
    #pragma unroll
    for (int mi = 0; mi < 4; mi++)
        #pragma unroll
        for (int ni = 0; ni < 6; ni++)
            #pragma unroll
            for (int q = 0; q < 4; q++) acc[mi][ni][q] = 0.f;

    auto issue_load = [&](int c) {
        const uint32_t sA = sbase + (c % NSTG) * STAGE_BYTES;
        const uint32_t sB = sA + A_BYTES;
        const float* asrc = wsrc + (size_t)c * CHUNK_A;
        #pragma unroll
        for (int r = 0; r < 4; r++) {
            int s = tid + r * 256;          // 1024 x 16B
            CP_ASYNC16(sA + (uint32_t)s * 16, asrc + s * 4);
        }
        const float* base;
        int rsg, nslot;
        if (mode == 1) {
            int kw = c >> 3, ci0 = (c & 7) << 5;
            base = g_xP + ((size_t)(b * CCH + ci0) * HH + h) * WP + (kw & ~3);
            rsg = HH * WP; nslot = 49;
        } else if (c < NC1) {
            int kh = c >> 3, ci0 = (c & 7) << 5;
            base = g_tmpP + ((size_t)(b * CCH + ci0) * HP + (h + kh)) * WW;
            rsg = HP * WW; nslot = 48;
        } else {
            int ci0 = (c - NC1) << 5;
            base = g_xC + ((size_t)(b * CCH + ci0) * HH + h) * WW;
            rsg = HH * WW; nslot = 48;
        }
        // 32 rows x nslot 16B slots (<= 1568 ops)
        #pragma unroll
        for (int r = 0; r < 7; r++) {
            int s = tid + r * 256;
            int row = s / 49, slot = s - row * 49;
            if (row < 32 && slot < nslot)
                CP_ASYNC16(sB + (uint32_t)(row * BSTRIDE + slot * 4) * 4,
                           base + (size_t)row * rsg + slot * 4);
        }
        CP_COMMIT();
    };

    issue_load(0);
    issue_load(1);

    for (int c = 0; c < NC; c++) {
        if (c + 1 < NC) { CP_WAIT_1(); } else { CP_WAIT_0(); }
        __syncthreads();

        const char* As = smem + (c % NSTG) * STAGE_BYTES;
        const float* Bs = (const float*)(As + A_BYTES);
        const int off0 = (mode == 1) ? ((c >> 3) & 3) : 0;

        #pragma unroll
        for (int k8b = 0; k8b < 4; k8b++) {
            uint32_t afr[4][4];
            #pragma unroll
            for (int mi = 0; mi < 4; mi++) {
                const uint4 va = *reinterpret_cast<const uint4*>(
                    As + ((((k8b * 2 + wm) * 4 + mi) * 32 + lane) << 4));
                afr[mi][0] = va.x; afr[mi][1] = va.y;
                afr[mi][2] = va.z; afr[mi][3] = va.w;
            }
            #pragma unroll
            for (int ni = 0; ni < 6; ni++) {
                const int nc = off0 + n0 + ni * 8 + g;
                uint32_t bfr[2];
                bfr[0] = __float_as_uint(Bs[(k8b * 8 + tq) * BSTRIDE + nc]);
                bfr[1] = __float_as_uint(Bs[(k8b * 8 + tq + 4) * BSTRIDE + nc]);
                #pragma unroll
                for (int mi = 0; mi < 4; mi++)
                    mma_tf32(acc[mi][ni], afr[mi], bfr);
            }
        }
        if (c + 2 < NC) issue_load(c + 2);   // stage (c+2)%3 last read in chunk c-1 -> safe
    }
    __syncthreads();

    // ---- epilogue ----
    if (mode == 1) {
        #pragma unroll
        for (int mi = 0; mi < 4; mi++) {
            const int coA = co0 + m0 + mi * 16 + g;
            const float bA = bias1[coA];
            const float bB = bias1[coA + 8];
            #pragma unroll
            for (int ni = 0; ni < 6; ni++) {
                const int w = n0 + ni * 8 + tq * 2;
                float2 vA = make_float2(tf32r(acc[mi][ni][0] + bA),
                                        tf32r(acc[mi][ni][1] + bA));
                float2 vB = make_float2(tf32r(acc[mi][ni][2] + bB),
                                        tf32r(acc[mi][ni][3] + bB));
                size_t rA = ((size_t)(b * CCH + coA) * HP + h + 2) * WW + w;
                size_t rB = ((size_t)(b * CCH + coA + 8) * HP + h + 2) * WW + w;
                *reinterpret_cast<float2*>(g_tmpP + rA) = vA;
                *reinterpret_cast<float2*>(g_tmpP + rB) = vB;
            }
        }
    } else {
        // NHWC out via smem transpose: 8 chunks of 24 pixels
        float* s = (float*)smem;                 // [24 pix][132]
        for (int j = 0; j < 8; j++) {
            __syncthreads();
            if (wn == (j >> 1)) {
                const int nb = (j & 1) * 3;      // ni base for this 24-px half
                #pragma unroll
                for (int mi = 0; mi < 4; mi++) {
                    const int clA = m0 + mi * 16 + g;
                    const float bA = bias1[co0 + clA] + bias2[co0 + clA];
                    const float bB = bias1[co0 + clA + 8] + bias2[co0 + clA + 8];
                    #pragma unroll
                    for (int nl = 0; nl < 3; nl++) {
                        const int ni = nb + nl;
                        const int nc = nl * 8 + tq * 2;
                        s[nc * 132 + clA]           = acc[mi][ni][0] + bA;
                        s[(nc + 1) * 132 + clA]     = acc[mi][ni][1] + bA;
                        s[nc * 132 + clA + 8]       = acc[mi][ni][2] + bB;
                        s[(nc + 1) * 132 + clA + 8] = acc[mi][ni][3] + bB;
                    }
                }
            }
            __syncthreads();
            #pragma unroll
            for (int r = 0; r < 3; r++) {
                int slot = r * 256 + tid;          // 768 = 24 x 32
                int p = slot >> 5, gg = slot & 31;
                float4 v = *reinterpret_cast<float4*>(&s[p * 132 + gg * 4]);
                size_t dst = ((size_t)(b * HH + h) * WW + j * 24 + p) * CCH
                           + co0 + gg * 4;
                *reinterpret_cast<float4*>(g_feat + dst) = v;
            }
        }
    }
}

// ---------------- align + residual ----------------
__global__ __launch_bounds__(256) void align_kernel(
    const float* __restrict__ x,
    const float* __restrict__ boxes,
    float* __restrict__ out)
{
    __shared__ float s[32][CCH + 1];
    const int nb = blockIdx.x;
    const int b  = nb / (HH * 6);
    const int r  = nb % (HH * 6);
    const int h  = r / 6;
    const int w0 = (r % 6) * 32;
    const int c  = threadIdx.x;
    const float* __restrict__ featb = g_feat + (size_t)b * HW * CCH;
    const float scale = 0.125f;

    #pragma unroll 1
    for (int p = 0; p < 32; p++) {
        const int pix = h * WW + (w0 + p);
        const float* __restrict__ bx = boxes + ((size_t)b * HW + pix) * 5;
        float yv = bx[0] * scale;
        float xv = bx[1] * scale;
        const bool valid = (yv >= -1.f) & (yv <= (float)HH) &
                           (xv >= -1.f) & (xv <= (float)WW);
        const float fc = featb[(size_t)pix * CCH + c];
        float v = 0.f;
        if (valid) {
            yv = fmaxf(yv, 0.f);
            xv = fmaxf(xv, 0.f);
            int yl = (int)floorf(yv);
            int xl = (int)floorf(xv);
            int yh, xh;
            if (yl >= HH - 1) { yl = HH - 1; yh = HH - 1; yv = (float)(HH - 1); }
            else              { yh = yl + 1; }
            if (xl >= WW - 1) { xl = WW - 1; xh = WW - 1; xv = (float)(WW - 1); }
            else              { xh = xl + 1; }
            const float ly = yv - (float)yl;
            const float lx = xv - (float)xl;
            const float hy = 1.f - ly;
            const float hx = 1.f - lx;
            const float f00 = featb[((size_t)yl * WW + xl) * CCH + c];
            const float f01 = featb[((size_t)yl * WW + xh) * CCH + c];
            const float f10 = featb[((size_t)yh * WW + xl) * CCH + c];
            const float f11 = featb[((size_t)yh * WW + xh) * CCH + c];
            v = hy * hx * f00 + hy * lx * f01 + ly * hx * f10 + ly * lx * f11;
        }
        s[p][c] = fc + v;
    }
    __syncthreads();
    const int wid = c / 32, lane = c % 32;
    const int w = w0 + lane;
    #pragma unroll 1
    for (int i = 0; i < 32; i++) {
        const int cc = wid * 32 + i;
        const size_t gi = ((size_t)(b * CCH + cc) * HH + h) * WW + w;
        out[gi] = x[gi] + s[lane][cc];
    }
}

// ---------------- launch ----------------
extern "C" void kernel_launch(void* const* d_in, const int* in_sizes, int n_in,
                              void* d_out, int out_size)
{
    const float* x     = (const float*)d_in[0];
    const float* boxes = (const float*)d_in[1];
    const float* w51   = (const float*)d_in[2];
    const float* b51   = (const float*)d_in[3];
    const float* w15   = (const float*)d_in[4];
    const float* b15   = (const float*)d_in[5];
    const float* w11   = (const float*)d_in[6];
    const float* b11   = (const float*)d_in[7];
    float* out = (float*)d_out;

    cudaFuncSetAttribute(gemm_mma, cudaFuncAttributeMaxDynamicSharedMemorySize, SMEM_DYN);

    pad_x_kernel   <<<8192, 256>>>(x);
    xc_kernel      <<<2048, 256>>>(x);
    zero_tmp_kernel<<<512, 256>>>();
    wpack_kernel   <<<768, 256>>>(w15, w51, w11);

    dim3 gg(NTOT / 192, 2);   // 384 x 2
    gemm_mma<<<gg, 256, SMEM_DYN>>>(1, b15, b15);
    gemm_mma<<<gg, 256, SMEM_DYN>>>(2, b51, b11);

    align_kernel<<<BATCH * HH * 6, 256>>>(x, boxes, out);
}

// round 17
// speedup vs baseline: 4.2179x; 4.2179x over previous
#include <cuda_runtime.h>
#include <cuda_bf16.h>
#include <cstdint>

// ---------------- problem constants ----------------
#define BATCH 2
#define CCH   256
#define HH    192
#define WW    192
#define HW    (HH * WW)            // 36864
#define NTOT  (BATCH * HW)         // 73728
#define WP    (WW + 4)             // 196
#define HP    (HH + 4)             // 196

// GEMM chunk geometry: CTA 128(co) x 96(pix), BK=32
#define NC1 40                     // K=1280
#define NC2 48                     // K=1536
#define CHUNK_A 4096               // floats per A chunk (32k x 128m), fragment-packed

// ---------------- device scratch ----------------
__device__ float g_xP  [BATCH * CCH * HH * WP + 64]; // NCHW w-padded(+2) tf32 (+slack)
__device__ float g_xC  [BATCH * CCH * HH * WW];      // NCHW plain tf32 (1x1 path)
__device__ float g_tmpP[BATCH * CCH * HP * WW];      // NCHW h-padded(+2) tf32
__device__ float g_feat[BATCH * HH * WW * CCH];      // NHWC fp32
__device__ float g_w15P[2 * NC1 * CHUNK_A];          // fragment-packed w15 (kw-major K)
__device__ float g_w51P[2 * NC2 * CHUNK_A];          // fragment-packed w51 (kh-major) + w11 tail

// ---------------- helpers ----------------
__device__ __forceinline__ float tf32r(float x) {
    uint32_t y;
    asm("cvt.rna.tf32.f32 %0, %1;" : "=r"(y) : "f"(x));
    return __uint_as_float(y);
}
__device__ __forceinline__ uint32_t smem_u32(const void* p) {
    uint32_t a;
    asm("{ .reg .u64 t; cvta.to.shared.u64 t, %1; cvt.u32.u64 %0, t; }" : "=r"(a) : "l"(p));
    return a;
}
#define CP_ASYNC16(dst, src) \
    asm volatile("cp.async.ca.shared.global [%0], [%1], 16;" :: "r"(dst), "l"(src))
#define CP_COMMIT()  asm volatile("cp.async.commit_group;")
#define CP_WAIT_1()  asm volatile("cp.async.wait_group 1;")
#define CP_WAIT_0()  asm volatile("cp.async.wait_group 0;")

__device__ __forceinline__ void mma_tf32(float* d, const uint32_t* a, const uint32_t* b) {
    asm volatile(
        "mma.sync.aligned.m16n8k8.row.col.f32.tf32.tf32.f32 "
        "{%0,%1,%2,%3}, {%4,%5,%6,%7}, {%8,%9}, {%0,%1,%2,%3};"
        : "+f"(d[0]), "+f"(d[1]), "+f"(d[2]), "+f"(d[3])
        : "r"(a[0]), "r"(a[1]), "r"(a[2]), "r"(a[3]), "r"(b[0]), "r"(b[1]));
}

// ---------------- prep kernels ----------------
__global__ __launch_bounds__(256) void pad_x_kernel(const float* __restrict__ x) {
    const int rows = BATCH * CCH * HH;
    const int wp = threadIdx.x;
    for (int row = blockIdx.x; row < rows; row += gridDim.x) {
        if (wp < WP) {
            float v = 0.f;
            if (wp >= 2 && wp < WW + 2)
                v = tf32r(x[(size_t)row * WW + (wp - 2)]);
            g_xP[(size_t)row * WP + wp] = v;
        }
    }
}

__global__ __launch_bounds__(256) void xc_kernel(const float* __restrict__ x) {
    const int N4 = BATCH * CCH * HW / 4;
    for (int id = blockIdx.x * blockDim.x + threadIdx.x; id < N4;
         id += gridDim.x * blockDim.x) {
        float4 v = reinterpret_cast<const float4*>(x)[id];
        v.x = tf32r(v.x); v.y = tf32r(v.y); v.z = tf32r(v.z); v.w = tf32r(v.w);
        reinterpret_cast<float4*>(g_xC)[id] = v;
    }
}

__global__ void zero_tmp_kernel() {
    const int N = BATCH * CCH * 4 * WW;
    for (int id = blockIdx.x * blockDim.x + threadIdx.x; id < N;
         id += gridDim.x * blockDim.x) {
        int w = id % WW, t = id / WW;
        int hs = t % 4,  bc = t / 4;
        int hpos = (hs < 2) ? hs : (hs + HH);
        g_tmpP[((size_t)bc * HP + hpos) * WW + w] = 0.f;
    }
}

// fragment-pack weights, K shift-major (gk = kshift*256 + ci), BK=32 chunks
__global__ void wpack_kernel(const float* __restrict__ w15,
                             const float* __restrict__ w51,
                             const float* __restrict__ w11) {
    const int N2 = 2 * NC2 * CHUNK_A;
    for (int id = blockIdx.x * blockDim.x + threadIdx.x; id < N2;
         id += gridDim.x * blockDim.x) {
        int reg  = id & 3;
        int lane = (id >> 2) & 31;
        int mi   = (id >> 7) & 3;
        int wm   = (id >> 9) & 1;
        int k8b  = (id >> 10) & 3;
        int rest = id >> 12;              // cb*NC2 + c
        int m_local = wm * 64 + mi * 16 + (lane >> 2) + ((reg & 1) << 3);
        int k_local = k8b * 8 + (lane & 3) + ((reg >> 1) << 2);
        int c  = rest % NC2;
        int cb = rest / NC2;
        int co = cb * 128 + m_local;
        int gk = c * 32 + k_local;
        float v;
        if (gk < 1280) {
            int kh = gk >> 8, ci = gk & 255;
            v = tf32r(w51[(co * CCH + ci) * 5 + kh]);
        } else {
            v = tf32r(w11[co * CCH + (gk - 1280)]);
        }
        g_w51P[id] = v;
    }
    const int N1 = 2 * NC1 * CHUNK_A;
    for (int id = blockIdx.x * blockDim.x + threadIdx.x; id < N1;
         id += gridDim.x * blockDim.x) {
        int reg  = id & 3;
        int lane = (id >> 2) & 31;
        int mi   = (id >> 7) & 3;
        int wm   = (id >> 9) & 1;
        int k8b  = (id >> 10) & 3;
        int rest = id >> 12;
        int c  = rest % NC1;
        int cb = rest / NC1;
        int m_local = wm * 64 + mi * 16 + (lane >> 2) + ((reg & 1) << 3);
        int k_local = k8b * 8 + (lane & 3) + ((reg >> 1) << 2);
        int co = cb * 128 + m_local;
        int gk = c * 32 + k_local;
        int kw = gk >> 8, ci = gk & 255;
        g_w15P[id] = tf32r(w15[(co * CCH + ci) * 5 + kw]);
    }
}

// ---------------- tf32 mma.sync GEMM ----------------
// stage: A packed 16384B + B row-major 32 x 104 floats (13312B); 3 stages dynamic smem
#define A_BYTES 16384
#define BSTRIDE 104                 // 104 % 32 == 8 -> conflict-free B reads
#define B_BYTES (32 * BSTRIDE * 4)  // 13312
#define STAGE_BYTES (A_BYTES + B_BYTES)   // 29696
#define NSTG 3
#define SMEM_DYN (NSTG * STAGE_BYTES)     // 89088

__global__ __launch_bounds__(256, 2) void gemm_mma(
    int mode,
    const float* __restrict__ bias1,
    const float* __restrict__ bias2)
{
    extern __shared__ __align__(16) char smem[];
    const uint32_t sbase = smem_u32(smem);

    const int tid  = threadIdx.x;
    const int lane = tid & 31;
    const int warp = tid >> 5;
    const int wm = warp >> 2;          // 0..1
    const int wn = warp & 3;           // 0..3
    const int m0 = wm * 64;
    const int n0 = wn * 24;
    const int g  = lane >> 2;          // 0..7
    const int tq = lane & 3;           // 0..3

    const int p0 = blockIdx.x * 96;
    const int b  = p0 / HW;
    const int rr = p0 % HW;
    const int h  = rr / WW;
    const int w0 = rr % WW;            // 0 or 96
    const int cb = blockIdx.y;
    const int co0 = cb * 128;

    const int NC = (mode == 1) ? NC1 : NC2;
    const float* __restrict__ wsrc =
        (mode == 1) ? (g_w15P + (size_t)cb * NC1 * CHUNK_A)
                    : (g_w51P + (size_t)cb * NC2 * CHUNK_A);

    float acc[4][3][4];
    #pragma unroll
    for (int mi = 0; mi < 4; mi++)
        #pragma unroll
        for (int ni = 0; ni < 3; ni++)
            #pragma unroll
            for (int q = 0; q < 4; q++) acc[mi][ni][q] = 0.f;

    auto issue_load = [&](int c) {
        const uint32_t sA = sbase + (c % NSTG) * STAGE_BYTES;
        const uint32_t sB = sA + A_BYTES;
        const float* asrc = wsrc + (size_t)c * CHUNK_A;
        #pragma unroll
        for (int r = 0; r < 4; r++) {
            int s = tid + r * 256;          // 1024 x 16B
            CP_ASYNC16(sA + (uint32_t)s * 16, asrc + s * 4);
        }
        const float* base;
        int rsg;
        bool full25;
        if (mode == 1) {
            int kw = c >> 3, ci0 = (c & 7) << 5;
            base = g_xP + ((size_t)(b * CCH + ci0) * HH + h) * WP + w0 + (kw & ~3);
            rsg = HH * WP; full25 = true;
        } else if (c < NC1) {
            int kh = c >> 3, ci0 = (c & 7) << 5;
            base = g_tmpP + ((size_t)(b * CCH + ci0) * HP + (h + kh)) * WW + w0;
            rsg = HP * WW; full25 = false;
        } else {
            int ci0 = (c - NC1) << 5;
            base = g_xC + ((size_t)(b * CCH + ci0) * HH + h) * WW + w0;
            rsg = HH * WW; full25 = false;
        }
        #pragma unroll
        for (int r = 0; r < 4; r++) {
            int s = tid + r * 256;          // 32 rows x 25 slots = 800
            if (s < 800) {
                int row = s / 25, slot = s - row * 25;
                if (full25 || slot < 24)
                    CP_ASYNC16(sB + (uint32_t)(row * BSTRIDE + slot * 4) * 4,
                               base + (size_t)row * rsg + slot * 4);
            }
        }
        CP_COMMIT();
    };

    issue_load(0);
    issue_load(1);

    for (int c = 0; c < NC; c++) {
        if (c + 1 < NC) { CP_WAIT_1(); } else { CP_WAIT_0(); }
        __syncthreads();

        // prefetch next-next chunk BEFORE compute: overlaps cp.async with MMA.
        // stage (c+2)%3 == (c-1)%3 was last read in iteration c-1; the barrier
        // above guarantees all warps finished those reads.
        if (c + 2 < NC) issue_load(c + 2);

        const char* As = smem + (c % NSTG) * STAGE_BYTES;
        const float* Bs = (const float*)(As + A_BYTES);
        const int off0 = (mode == 1) ? ((c >> 3) & 3) : 0;

        #pragma unroll
        for (int k8b = 0; k8b < 4; k8b++) {
            uint32_t afr[4][4];
            #pragma unroll
            for (int mi = 0; mi < 4; mi++) {
                const uint4 va = *reinterpret_cast<const uint4*>(
                    As + ((((k8b * 2 + wm) * 4 + mi) * 32 + lane) << 4));
                afr[mi][0] = va.x; afr[mi][1] = va.y;
                afr[mi][2] = va.z; afr[mi][3] = va.w;
            }
            #pragma unroll
            for (int ni = 0; ni < 3; ni++) {
                const int nc = off0 + n0 + ni * 8 + g;
                uint32_t bfr[2];
                bfr[0] = __float_as_uint(Bs[(k8b * 8 + tq) * BSTRIDE + nc]);
                bfr[1] = __float_as_uint(Bs[(k8b * 8 + tq + 4) * BSTRIDE + nc]);
                #pragma unroll
                for (int mi = 0; mi < 4; mi++)
                    mma_tf32(acc[mi][ni], afr[mi], bfr);
            }
        }
    }
    __syncthreads();

    // ---- epilogue ----
    if (mode == 1) {
        #pragma unroll
        for (int mi = 0; mi < 4; mi++) {
            const int coA = co0 + m0 + mi * 16 + g;
            const float bA = bias1[coA];
            const float bB = bias1[coA + 8];
            #pragma unroll
            for (int ni = 0; ni < 3; ni++) {
                const int w = w0 + n0 + ni * 8 + tq * 2;
                float2 vA = make_float2(tf32r(acc[mi][ni][0] + bA),
                                        tf32r(acc[mi][ni][1] + bA));
                float2 vB = make_float2(tf32r(acc[mi][ni][2] + bB),
                                        tf32r(acc[mi][ni][3] + bB));
                size_t rA = ((size_t)(b * CCH + coA) * HP + h + 2) * WW + w;
                size_t rB = ((size_t)(b * CCH + coA + 8) * HP + h + 2) * WW + w;
                *reinterpret_cast<float2*>(g_tmpP + rA) = vA;
                *reinterpret_cast<float2*>(g_tmpP + rB) = vB;
            }
        }
    } else {
        float* s = (float*)smem;                 // [24 pix][132]
        for (int j = 0; j < 4; j++) {
            __syncthreads();
            if (wn == j) {
                #pragma unroll
                for (int mi = 0; mi < 4; mi++) {
                    const int clA = m0 + mi * 16 + g;
                    const float bA = bias1[co0 + clA] + bias2[co0 + clA];
                    const float bB = bias1[co0 + clA + 8] + bias2[co0 + clA + 8];
                    #pragma unroll
                    for (int ni = 0; ni < 3; ni++) {
                        const int nc = ni * 8 + tq * 2;
                        s[nc * 132 + clA]           = acc[mi][ni][0] + bA;
                        s[(nc + 1) * 132 + clA]     = acc[mi][ni][1] + bA;
                        s[nc * 132 + clA + 8]       = acc[mi][ni][2] + bB;
                        s[(nc + 1) * 132 + clA + 8] = acc[mi][ni][3] + bB;
                    }
                }
            }
            __syncthreads();
            #pragma unroll
            for (int r = 0; r < 3; r++) {
                int slot = r * 256 + tid;          // 768 = 24 x 32
                int p = slot >> 5, gg = slot & 31;
                float4 v = *reinterpret_cast<float4*>(&s[p * 132 + gg * 4]);
                size_t dst = ((size_t)(b * HH + h) * WW + w0 + j * 24 + p) * CCH
                           + co0 + gg * 4;
                *reinterpret_cast<float4*>(g_feat + dst) = v;
            }
        }
    }
}

// ---------------- align + residual ----------------
__global__ __launch_bounds__(256) void align_kernel(
    const float* __restrict__ x,
    const float* __restrict__ boxes,
    float* __restrict__ out)
{
    __shared__ float s[32][CCH + 1];
    const int nb = blockIdx.x;
    const int b  = nb / (HH * 6);
    const int r  = nb % (HH * 6);
    const int h  = r / 6;
    const int w0 = (r % 6) * 32;
    const int c  = threadIdx.x;
    const float* __restrict__ featb = g_feat + (size_t)b * HW * CCH;
    const float scale = 0.125f;

    // unroll 2: independent pixel iterations -> double outstanding loads (MLP)
    #pragma unroll 2
    for (int p = 0; p < 32; p++) {
        const int pix = h * WW + (w0 + p);
        const float* __restrict__ bx = boxes + ((size_t)b * HW + pix) * 5;
        float yv = bx[0] * scale;
        float xv = bx[1] * scale;
        const bool valid = (yv >= -1.f) & (yv <= (float)HH) &
                           (xv >= -1.f) & (xv <= (float)WW);
        const float fc = featb[(size_t)pix * CCH + c];
        float v = 0.f;
        if (valid) {
            yv = fmaxf(yv, 0.f);
            xv = fmaxf(xv, 0.f);
            int yl = (int)floorf(yv);
            int xl = (int)floorf(xv);
            int yh, xh;
            if (yl >= HH - 1) { yl = HH - 1; yh = HH - 1; yv = (float)(HH - 1); }
            else              { yh = yl + 1; }
            if (xl >= WW - 1) { xl = WW - 1; xh = WW - 1; xv = (float)(WW - 1); }
            else              { xh = xl + 1; }
            const float ly = yv - (float)yl;
            const float lx = xv - (float)xl;
            const float hy = 1.f - ly;
            const float hx = 1.f - lx;
            const float f00 = featb[((size_t)yl * WW + xl) * CCH + c];
            const float f01 = featb[((size_t)yl * WW + xh) * CCH + c];
            const float f10 = featb[((size_t)yh * WW + xl) * CCH + c];
            const float f11 = featb[((size_t)yh * WW + xh) * CCH + c];
            v = hy * hx * f00 + hy * lx * f01 + ly * hx * f10 + ly * lx * f11;
        }
        s[p][c] = fc + v;
    }
    __syncthreads();
    const int wid = c / 32, lane = c % 32;
    const int w = w0 + lane;
    #pragma unroll 2
    for (int i = 0; i < 32; i++) {
        const int cc = wid * 32 + i;
        const size_t gi = ((size_t)(b * CCH + cc) * HH + h) * WW + w;
        out[gi] = x[gi] + s[lane][cc];
    }
}

// ---------------- launch ----------------
extern "C" void kernel_launch(void* const* d_in, const int* in_sizes, int n_in,
                              void* d_out, int out_size)
{
    const float* x     = (const float*)d_in[0];
    const float* boxes = (const float*)d_in[1];
    const float* w51   = (const float*)d_in[2];
    const float* b51   = (const float*)d_in[3];
    const float* w15   = (const float*)d_in[4];
    const float* b15   = (const float*)d_in[5];
    const float* w11   = (const float*)d_in[6];
    const float* b11   = (const float*)d_in[7];
    float* out = (float*)d_out;

    cudaFuncSetAttribute(gemm_mma, cudaFuncAttributeMaxDynamicSharedMemorySize, SMEM_DYN);

    pad_x_kernel   <<<8192, 256>>>(x);
    xc_kernel      <<<2048, 256>>>(x);
    zero_tmp_kernel<<<512, 256>>>();
    wpack_kernel   <<<768, 256>>>(w15, w51, w11);

    dim3 gg(NTOT / 96, 2);   // 768 x 2
    gemm_mma<<<gg, 256, SMEM_DYN>>>(1, b15, b15);
    gemm_mma<<<gg, 256, SMEM_DYN>>>(2, b51, b11);

    align_kernel<<<BATCH * HH * 6, 256>>>(x, boxes, out);
}